// round 2
// baseline (speedup 1.0000x reference)
#include <cuda_runtime.h>
#include <cuda_bf16.h>
#include <cstdint>

// Problem dims (fixed for this dataset instance)
#define NB 256   // batch
#define NS 256   // seq
#define ND 256   // model dim
#define NH 4     // heads
#define DH 64    // head dim

// ---------------------------------------------------------------------------
// Device scratch (kept SMALL: ~34 MB total; prior 202 MB OOM'd the harness)
// ---------------------------------------------------------------------------
__device__ __nv_bfloat16 g_ctx[NB * NS * ND];       // [b*s][d] attention output
__device__ __nv_bfloat16 g_WqkvT[3 * ND * ND];      // [n(=mat*256+col)][k] bf16
__device__ __nv_bfloat16 g_WoT[ND * ND];            // [n][k] bf16
__device__ float g_bias_qkv[3 * ND];
__device__ float g_addvec[NB * ND];                 // scale*obj_emb[rank[b]]
__device__ int   g_rank[NB];
__device__ int   g_big[NB];                         // gsize > 1

// ---------------------------------------------------------------------------
// PTX helpers
// ---------------------------------------------------------------------------
__device__ __forceinline__ uint32_t sptr(const void* p) {
    return static_cast<uint32_t>(__cvta_generic_to_shared(p));
}
__device__ __forceinline__ void ldm_x4(uint32_t r[4], uint32_t a) {
    asm volatile("ldmatrix.sync.aligned.m8n8.x4.shared.b16 {%0,%1,%2,%3}, [%4];\n"
                 : "=r"(r[0]), "=r"(r[1]), "=r"(r[2]), "=r"(r[3]) : "r"(a));
}
__device__ __forceinline__ void ldm_x2(uint32_t r[2], uint32_t a) {
    asm volatile("ldmatrix.sync.aligned.m8n8.x2.shared.b16 {%0,%1}, [%2];\n"
                 : "=r"(r[0]), "=r"(r[1]) : "r"(a));
}
__device__ __forceinline__ void ldm_x2t(uint32_t r[2], uint32_t a) {
    asm volatile("ldmatrix.sync.aligned.m8n8.x2.trans.shared.b16 {%0,%1}, [%2];\n"
                 : "=r"(r[0]), "=r"(r[1]) : "r"(a));
}
__device__ __forceinline__ void mma16816(float c[4], const uint32_t a[4], const uint32_t b[2]) {
    asm volatile(
        "mma.sync.aligned.m16n8k16.row.col.f32.bf16.bf16.f32 "
        "{%0,%1,%2,%3}, {%4,%5,%6,%7}, {%8,%9}, {%0,%1,%2,%3};\n"
        : "+f"(c[0]), "+f"(c[1]), "+f"(c[2]), "+f"(c[3])
        : "r"(a[0]), "r"(a[1]), "r"(a[2]), "r"(a[3]), "r"(b[0]), "r"(b[1]));
}
__device__ __forceinline__ uint32_t packbf(float x, float y) {
    __nv_bfloat162 t = __floats2bfloat162_rn(x, y);
    return *reinterpret_cast<uint32_t*>(&t);
}

// ---------------------------------------------------------------------------
// Kernel 1: rank / group-size from img_ids  (one block of NB threads)
// ---------------------------------------------------------------------------
__global__ void prep_rank(const int* __restrict__ ids, int max_obj) {
    __shared__ int sh[NB];
    int t = threadIdx.x;
    sh[t] = ids[t];
    __syncthreads();
    int id = sh[t];
    int rank = 0, size = 0;
    #pragma unroll 8
    for (int j = 0; j < NB; j++) {
        int same = (sh[j] == id);
        size += same;
        rank += (j < t) ? same : 0;
    }
    g_rank[t] = (rank < max_obj) ? rank : (max_obj - 1);   // jax clamp semantics
    g_big[t]  = (size > 1);
}

// ---------------------------------------------------------------------------
// Kernel 2: per-batch additive vector = scale * obj_emb[rank[b]]
// ---------------------------------------------------------------------------
__global__ void prep_addvec(const float* __restrict__ obj_emb,
                            const float* __restrict__ scale) {
    int b = blockIdx.x, d = threadIdx.x;
    g_addvec[b * ND + d] = scale[0] * obj_emb[g_rank[b] * ND + d];
}

// ---------------------------------------------------------------------------
// Kernel 3: convert / transpose weights to bf16 [n][k], concat biases
// ---------------------------------------------------------------------------
__global__ void conv_weights(const float* __restrict__ Wq, const float* __restrict__ Wk,
                             const float* __restrict__ Wv, const float* __restrict__ Wo,
                             const float* __restrict__ bq, const float* __restrict__ bk,
                             const float* __restrict__ bv) {
    int idx = blockIdx.x * 256 + threadIdx.x;     // [0, 3*65536)
    int row = idx >> 8;                            // n index [0,768)
    int kk  = idx & 255;
    int mat = row >> 8;
    int n   = row & 255;
    const float* W = (mat == 0) ? Wq : ((mat == 1) ? Wk : Wv);
    g_WqkvT[idx] = __float2bfloat16(W[kk * ND + n]);
    if (idx < ND * ND)
        g_WoT[idx] = __float2bfloat16(Wo[(idx & 255) * ND + (idx >> 8)]);
    if (idx < 3 * ND)
        g_bias_qkv[idx] = (idx < 256) ? bq[idx] : ((idx < 512) ? bk[idx - 256] : bv[idx - 512]);
}

// ---------------------------------------------------------------------------
// Fused kernel: one block per (b,h). 256 threads = 8 warps (32 q-rows each).
//   Phase 1: Es = bf16(batch_seq[b] + addvec[b])           (smem, 256x264)
//   Phase 2: K,V = Es @ W  -> smem;  Q = Es @ W -> registers (A-frag)
//   Phase 3: flash attention over 256 keys, P in registers
//   Phase 4: ctx -> g_ctx
// Dynamic smem: Es 135168 + Ks 36864 + Vs 36864 + Bs 17408 = 226304 B
// ---------------------------------------------------------------------------
#define ES_OFF 0
#define KS_OFF (256 * 264 * 2)
#define VS_OFF (KS_OFF + 256 * 72 * 2)
#define BS_OFF (VS_OFF + 256 * 72 * 2)
#define FUSED_SMEM (BS_OFF + 64 * 136 * 2)

__global__ __launch_bounds__(256, 1) void fused_bh(const float* __restrict__ bs) {
    extern __shared__ char smraw[];
    __nv_bfloat16 (*Es)[264] = reinterpret_cast<__nv_bfloat16(*)[264]>(smraw + ES_OFF);
    __nv_bfloat16 (*Ks)[72]  = reinterpret_cast<__nv_bfloat16(*)[72]>(smraw + KS_OFF);
    __nv_bfloat16 (*Vs)[72]  = reinterpret_cast<__nv_bfloat16(*)[72]>(smraw + VS_OFF);
    __nv_bfloat16 (*Bs)[136] = reinterpret_cast<__nv_bfloat16(*)[136]>(smraw + BS_OFF);

    const int bh = blockIdx.x;
    const int b = bh >> 2, h = bh & 3;
    const int tid = threadIdx.x, lane = tid & 31, warp = tid >> 5;
    const int g = lane >> 2, tig = lane & 3;
    const int li = lane & 7, sel = lane >> 3, l16 = lane & 15;

    // ---------------- Phase 1: enhanced features into smem -----------------
    const float* src = bs + (size_t)b * NS * ND;
    #pragma unroll 4
    for (int i = 0; i < 64; i++) {
        int e4 = i * 256 + tid;            // vec4 index; 64 vec4 per row
        int row = e4 >> 6;
        int c = (e4 & 63) << 2;
        float4 x = *reinterpret_cast<const float4*>(src + row * ND + c);
        float4 a = *reinterpret_cast<const float4*>(&g_addvec[b * ND + c]);
        uint2 pk;
        pk.x = packbf(x.x + a.x, x.y + a.y);
        pk.y = packbf(x.z + a.z, x.w + a.w);
        *reinterpret_cast<uint2*>(&Es[row][c]) = pk;
    }
    __syncthreads();

    // ---------------- Phase 2: three GEMMs (K, V, then Q) ------------------
    uint32_t qf[2][4][4];                  // Q A-fragments (persist to attention)

    #pragma unroll 1
    for (int it = 0; it < 3; it++) {
        const int msel = (it == 0) ? 1 : ((it == 1) ? 2 : 0);   // K, V, Q
        float acc[2][8][4];
        #pragma unroll
        for (int i = 0; i < 2; i++)
            #pragma unroll
            for (int j = 0; j < 8; j++)
                #pragma unroll
                for (int c = 0; c < 4; c++) acc[i][j][c] = 0.f;

        #pragma unroll 1
        for (int kh = 0; kh < 2; kh++) {
            // stage B half: WT rows [msel*256+h*64 .. +63], k-cols [kh*128 ..]
            {
                int r = tid >> 2;
                int cb = (tid & 3) * 32;
                const __nv_bfloat16* wsrc =
                    g_WqkvT + ((size_t)(msel * ND + h * DH + r)) * ND + kh * 128 + cb;
                #pragma unroll
                for (int j = 0; j < 4; j++)
                    *reinterpret_cast<uint4*>(&Bs[r][cb + j * 8]) =
                        *reinterpret_cast<const uint4*>(wsrc + j * 8);
            }
            __syncthreads();
            #pragma unroll
            for (int ks = 0; ks < 8; ks++) {
                uint32_t a[2][4];
                ldm_x4(a[0], sptr(&Es[warp * 32 +      (sel & 1) * 8 + li][kh * 128 + ks * 16 + (sel >> 1) * 8]));
                ldm_x4(a[1], sptr(&Es[warp * 32 + 16 + (sel & 1) * 8 + li][kh * 128 + ks * 16 + (sel >> 1) * 8]));
                #pragma unroll
                for (int nj = 0; nj < 8; nj++) {
                    uint32_t bfr[2];
                    ldm_x2(bfr, sptr(&Bs[nj * 8 + li][ks * 16 + (l16 >> 3) * 8]));
                    mma16816(acc[0][nj], a[0], bfr);
                    mma16816(acc[1][nj], a[1], bfr);
                }
            }
            __syncthreads();
        }

        // epilogue
        if (it < 2) {
            __nv_bfloat16 (*dst)[72] = (it == 0) ? Ks : Vs;
            #pragma unroll
            for (int mi = 0; mi < 2; mi++)
                #pragma unroll
                for (int nj = 0; nj < 8; nj++)
                    #pragma unroll
                    for (int p = 0; p < 2; p++) {
                        int row = warp * 32 + mi * 16 + p * 8 + g;
                        int col = nj * 8 + tig * 2;
                        float b0 = g_bias_qkv[msel * ND + h * DH + col];
                        float b1 = g_bias_qkv[msel * ND + h * DH + col + 1];
                        *reinterpret_cast<__nv_bfloat162*>(&dst[row][col]) =
                            __floats2bfloat162_rn(acc[mi][nj][p * 2] + b0,
                                                  acc[mi][nj][p * 2 + 1] + b1);
                    }
        } else {
            // Q: C-frag -> A-frag identity packing, bias added first
            #pragma unroll
            for (int mi = 0; mi < 2; mi++)
                #pragma unroll
                for (int kd = 0; kd < 4; kd++) {
                    float b0 = g_bias_qkv[h * DH + kd * 16 + tig * 2];
                    float b1 = g_bias_qkv[h * DH + kd * 16 + tig * 2 + 1];
                    float b2 = g_bias_qkv[h * DH + kd * 16 + 8 + tig * 2];
                    float b3 = g_bias_qkv[h * DH + kd * 16 + 8 + tig * 2 + 1];
                    qf[mi][kd][0] = packbf(acc[mi][2 * kd][0] + b0, acc[mi][2 * kd][1] + b1);
                    qf[mi][kd][1] = packbf(acc[mi][2 * kd][2] + b0, acc[mi][2 * kd][3] + b1);
                    qf[mi][kd][2] = packbf(acc[mi][2 * kd + 1][0] + b2, acc[mi][2 * kd + 1][1] + b3);
                    qf[mi][kd][3] = packbf(acc[mi][2 * kd + 1][2] + b2, acc[mi][2 * kd + 1][3] + b3);
                }
        }
    }

    // ---------------- Phase 3: flash attention -----------------------------
    float O[2][8][4];
    #pragma unroll
    for (int i = 0; i < 2; i++)
        #pragma unroll
        for (int j = 0; j < 8; j++)
            #pragma unroll
            for (int c = 0; c < 4; c++) O[i][j][c] = 0.f;
    float mrow[2][2] = {{-1e30f, -1e30f}, {-1e30f, -1e30f}};
    float lrow[2][2] = {{0.f, 0.f}, {0.f, 0.f}};
    const float SC = 0.125f * 1.4426950408889634f;   // (1/sqrt(dh)) * log2(e)

    #pragma unroll 1
    for (int kc = 0; kc < 4; kc++) {                 // 4 chunks of 64 keys
        float s[2][8][4];
        #pragma unroll
        for (int i = 0; i < 2; i++)
            #pragma unroll
            for (int j = 0; j < 8; j++)
                #pragma unroll
                for (int c = 0; c < 4; c++) s[i][j][c] = 0.f;

        // S = Q K^T
        #pragma unroll
        for (int kd = 0; kd < 4; kd++)
            #pragma unroll
            for (int nj = 0; nj < 8; nj++) {
                uint32_t bfr[2];
                ldm_x2(bfr, sptr(&Ks[kc * 64 + nj * 8 + li][kd * 16 + (l16 >> 3) * 8]));
                mma16816(s[0][nj], qf[0][kd], bfr);
                mma16816(s[1][nj], qf[1][kd], bfr);
            }

        // Online softmax
        #pragma unroll
        for (int mi = 0; mi < 2; mi++)
            #pragma unroll
            for (int rs = 0; rs < 2; rs++) {
                float mx = -1e30f;
                #pragma unroll
                for (int nj = 0; nj < 8; nj++)
                    mx = fmaxf(mx, fmaxf(s[mi][nj][rs * 2], s[mi][nj][rs * 2 + 1]));
                mx = fmaxf(mx, __shfl_xor_sync(0xffffffffu, mx, 1));
                mx = fmaxf(mx, __shfl_xor_sync(0xffffffffu, mx, 2));
                float mnew = fmaxf(mrow[mi][rs], mx);
                float alpha = exp2f((mrow[mi][rs] - mnew) * SC);
                mrow[mi][rs] = mnew;
                float sum = 0.f;
                #pragma unroll
                for (int nj = 0; nj < 8; nj++) {
                    float p0 = exp2f((s[mi][nj][rs * 2]     - mnew) * SC);
                    float p1 = exp2f((s[mi][nj][rs * 2 + 1] - mnew) * SC);
                    s[mi][nj][rs * 2] = p0;
                    s[mi][nj][rs * 2 + 1] = p1;
                    sum += p0 + p1;
                }
                sum += __shfl_xor_sync(0xffffffffu, sum, 1);
                sum += __shfl_xor_sync(0xffffffffu, sum, 2);
                lrow[mi][rs] = lrow[mi][rs] * alpha + sum;
                #pragma unroll
                for (int nj = 0; nj < 8; nj++) {
                    O[mi][nj][rs * 2]     *= alpha;
                    O[mi][nj][rs * 2 + 1] *= alpha;
                }
            }

        // O += P V   (P: C-frag -> A-frag identity; V via ldmatrix.trans)
        #pragma unroll
        for (int kk = 0; kk < 4; kk++) {
            uint32_t pa[2][4];
            #pragma unroll
            for (int mi = 0; mi < 2; mi++) {
                pa[mi][0] = packbf(s[mi][2 * kk][0],     s[mi][2 * kk][1]);
                pa[mi][1] = packbf(s[mi][2 * kk][2],     s[mi][2 * kk][3]);
                pa[mi][2] = packbf(s[mi][2 * kk + 1][0], s[mi][2 * kk + 1][1]);
                pa[mi][3] = packbf(s[mi][2 * kk + 1][2], s[mi][2 * kk + 1][3]);
            }
            #pragma unroll
            for (int nj = 0; nj < 8; nj++) {
                uint32_t bv2[2];
                ldm_x2t(bv2, sptr(&Vs[kc * 64 + kk * 16 + l16][nj * 8]));
                mma16816(O[0][nj], pa[0], bv2);
                mma16816(O[1][nj], pa[1], bv2);
            }
        }
    }

    // ---------------- Phase 4: normalize + write ctx -----------------------
    #pragma unroll
    for (int mi = 0; mi < 2; mi++)
        #pragma unroll
        for (int rs = 0; rs < 2; rs++) {
            float inv = 1.f / lrow[mi][rs];
            int row = warp * 32 + mi * 16 + rs * 8 + g;
            #pragma unroll
            for (int nj = 0; nj < 8; nj++) {
                int col = nj * 8 + tig * 2;
                *reinterpret_cast<__nv_bfloat162*>(
                    &g_ctx[((size_t)b * NS + row) * ND + h * DH + col]) =
                    __floats2bfloat162_rn(O[mi][nj][rs * 2] * inv,
                                          O[mi][nj][rs * 2 + 1] * inv);
            }
        }
}

// ---------------------------------------------------------------------------
// Shared 128x128x256 bf16 GEMM mainloop for the output projection
// ---------------------------------------------------------------------------
__device__ __forceinline__ void mm_tile(const __nv_bfloat16* __restrict__ A,
                                        const __nv_bfloat16* __restrict__ Bt,
                                        float acc[2][8][4]) {
    __shared__ __nv_bfloat16 As[128][40];
    __shared__ __nv_bfloat16 Bsh[128][40];
    const int tid  = threadIdx.x;
    const int lane = tid & 31;
    const int warp = tid >> 5;
    const int wm = warp >> 1, wn = warp & 1;
    const int r0 = tid >> 2, c0 = (tid & 3) * 8;
    const int li = lane & 7, sel = lane >> 3, l16 = lane & 15;

    for (int kt = 0; kt < 8; kt++) {
        const __nv_bfloat16* Ag = A + kt * 32;
        const __nv_bfloat16* Bg = Bt + kt * 32;
        *reinterpret_cast<uint4*>(&As[r0][c0])       = *reinterpret_cast<const uint4*>(&Ag[r0 * 256 + c0]);
        *reinterpret_cast<uint4*>(&As[r0 + 64][c0])  = *reinterpret_cast<const uint4*>(&Ag[(r0 + 64) * 256 + c0]);
        *reinterpret_cast<uint4*>(&Bsh[r0][c0])      = *reinterpret_cast<const uint4*>(&Bg[r0 * 256 + c0]);
        *reinterpret_cast<uint4*>(&Bsh[r0 + 64][c0]) = *reinterpret_cast<const uint4*>(&Bg[(r0 + 64) * 256 + c0]);
        __syncthreads();
        #pragma unroll
        for (int ks = 0; ks < 2; ks++) {
            uint32_t a[2][4];
            ldm_x4(a[0], sptr(&As[wm * 32 +      li + (sel & 1) * 8][ks * 16 + (sel >> 1) * 8]));
            ldm_x4(a[1], sptr(&As[wm * 32 + 16 + li + (sel & 1) * 8][ks * 16 + (sel >> 1) * 8]));
            #pragma unroll
            for (int nj = 0; nj < 8; nj++) {
                uint32_t b[2];
                ldm_x2(b, sptr(&Bsh[wn * 64 + nj * 8 + li][ks * 16 + (l16 >> 3) * 8]));
                mma16816(acc[0][nj], a[0], b);
                mma16816(acc[1][nj], a[1], b);
            }
        }
        __syncthreads();
    }
}

// ---------------------------------------------------------------------------
// Kernel: out = (gsize>1) ? batch_seq + ctx@Wo + bo : batch_seq
// ---------------------------------------------------------------------------
__global__ __launch_bounds__(256) void gemm_out(const float* __restrict__ bs,
                                                const float* __restrict__ bo,
                                                float* __restrict__ out) {
    float acc[2][8][4];
    #pragma unroll
    for (int i = 0; i < 2; i++)
        #pragma unroll
        for (int j = 0; j < 8; j++)
            #pragma unroll
            for (int c = 0; c < 4; c++) acc[i][j][c] = 0.f;

    const int m0 = blockIdx.x * 128;
    const int n0 = blockIdx.y * 128;
    mm_tile(g_ctx + (size_t)m0 * 256, g_WoT + (size_t)n0 * 256, acc);

    const int lane = threadIdx.x & 31, warp = threadIdx.x >> 5;
    const int wm = warp >> 1, wn = warp & 1;
    const int g = lane >> 2, tig = lane & 3;
    const int big = g_big[m0 >> 8];    // b constant within the block's 128 rows
    #pragma unroll
    for (int mi = 0; mi < 2; mi++)
        #pragma unroll
        for (int nj = 0; nj < 8; nj++)
            #pragma unroll
            for (int p = 0; p < 2; p++) {
                int m = m0 + wm * 32 + mi * 16 + p * 8 + g;
                int n = n0 + wn * 64 + nj * 8 + tig * 2;
                int idx = m * ND + n;
                float2 base = *reinterpret_cast<const float2*>(&bs[idx]);
                float2 o;
                if (big) {
                    o.x = base.x + acc[mi][nj][p * 2]     + bo[n];
                    o.y = base.y + acc[mi][nj][p * 2 + 1] + bo[n + 1];
                } else {
                    o = base;
                }
                *reinterpret_cast<float2*>(&out[idx]) = o;
            }
}

// ---------------------------------------------------------------------------
// Launch
// ---------------------------------------------------------------------------
extern "C" void kernel_launch(void* const* d_in, const int* in_sizes, int n_in,
                              void* d_out, int out_size) {
    const float* bs    = (const float*)d_in[0];
    const int*   ids   = (const int*)d_in[1];
    const float* Wq    = (const float*)d_in[2];
    const float* Wk    = (const float*)d_in[3];
    const float* Wv    = (const float*)d_in[4];
    const float* Wo    = (const float*)d_in[5];
    const float* bq    = (const float*)d_in[6];
    const float* bk    = (const float*)d_in[7];
    const float* bv    = (const float*)d_in[8];
    const float* bo    = (const float*)d_in[9];
    const float* obj   = (const float*)d_in[10];
    const float* scale = (const float*)d_in[11];
    const int max_obj = in_sizes[10] / ND;

    static bool configured = false;
    if (!configured) {
        cudaFuncSetAttribute(fused_bh, cudaFuncAttributeMaxDynamicSharedMemorySize, FUSED_SMEM);
        configured = true;
    }

    prep_rank<<<1, NB>>>(ids, max_obj);
    prep_addvec<<<NB, ND>>>(obj, scale);
    conv_weights<<<768, 256>>>(Wq, Wk, Wv, Wo, bq, bk, bv);
    fused_bh<<<NB * NH, 256, FUSED_SMEM>>>(bs);
    gemm_out<<<dim3(512, 2), 256>>>(bs, bo, (float*)d_out);
}